// round 11
// baseline (speedup 1.0000x reference)
#include <cuda_runtime.h>

// Sobel |gx|+|gy|+eps over (32,1,1024,1024) f32, SAME zero padding.
// 256-bit loads: each thread owns an 8-float column, block (128 thr) covers a
// full 1024-wide row, RPT=16 rows per block. 3-row rolling register window,
// raw rows prefetched 2 iterations ahead via ld.global.nc.v8.b32 (1KB/warp
// per load in flight). Horizontal halo via shuffle + warp-edge scalar loads.

#define IMG_W 1024
#define IMG_H 1024
#define TPB   128           // threads per block = float8 columns per row
#define RPT   16            // output rows per block
#define RB    (IMG_H / RPT) // 64 row-blocks per image

struct Raw8 {
    float c[8];
    float e;   // lane 0: left halo; lane 31: right halo; others unused
};

__device__ __forceinline__ Raw8 load_raw8(const float* __restrict__ base,
                                          bool in, int tid, int lane) {
    Raw8 o;
    #pragma unroll
    for (int j = 0; j < 8; j++) o.c[j] = 0.0f;
    o.e = 0.0f;
    if (in) {
        unsigned r0, r1, r2, r3, r4, r5, r6, r7;
        asm volatile(
            "ld.global.nc.v8.b32 {%0,%1,%2,%3,%4,%5,%6,%7}, [%8];"
            : "=r"(r0), "=r"(r1), "=r"(r2), "=r"(r3),
              "=r"(r4), "=r"(r5), "=r"(r6), "=r"(r7)
            : "l"(base));
        o.c[0] = __uint_as_float(r0); o.c[1] = __uint_as_float(r1);
        o.c[2] = __uint_as_float(r2); o.c[3] = __uint_as_float(r3);
        o.c[4] = __uint_as_float(r4); o.c[5] = __uint_as_float(r5);
        o.c[6] = __uint_as_float(r6); o.c[7] = __uint_as_float(r7);
        if (lane == 0) {
            if (tid > 0) o.e = __ldg(base - 1);
        } else if (lane == 31) {
            if (tid < TPB - 1) o.e = __ldg(base + 8);
        }
    }
    return o;
}

__device__ __forceinline__ void expand8(const Raw8& rr, int lane, float v[10]) {
    float left  = __shfl_up_sync(0xFFFFFFFFu, rr.c[7], 1);
    float right = __shfl_down_sync(0xFFFFFFFFu, rr.c[0], 1);
    if (lane == 0)  left  = rr.e;
    if (lane == 31) right = rr.e;
    v[0] = left;
    #pragma unroll
    for (int j = 0; j < 8; j++) v[j + 1] = rr.c[j];
    v[9] = right;
}

__global__ void __launch_bounds__(TPB, 8)
sobel_grad_kernel(const float* __restrict__ x, float* __restrict__ out) {
    int tid  = threadIdx.x;            // float8 column (0..127)
    int lane = tid & 31;
    int bid  = blockIdx.x;
    int rb   = bid & (RB - 1);         // row block (0..63)
    int n    = bid >> 6;               // image     (0..31)

    int row0 = rb * RPT;
    const float* ibase = x + (size_t)n * IMG_H * IMG_W + (size_t)tid * 8;
    float*       obase = out + (size_t)n * IMG_H * IMG_W + (size_t)tid * 8
                             + (size_t)row0 * IMG_W;

    float top[10], mid[10], bot[10];
    Raw8 praw;

    // Prologue: rows row0-1 .. row0+1 expanded, row0+2 raw-prefetched.
    {
        const float* p = ibase + (size_t)(row0 - 1) * IMG_W;
        Raw8 r0 = load_raw8(p,             row0 - 1 >= 0,    tid, lane);
        Raw8 r1 = load_raw8(p + IMG_W,     true,             tid, lane);
        Raw8 r2 = load_raw8(p + 2 * IMG_W, true,             tid, lane);
        praw    = load_raw8(p + 3 * IMG_W, row0 + 2 < IMG_H, tid, lane);
        expand8(r0, lane, top);
        expand8(r1, lane, mid);
        expand8(r2, lane, bot);
    }

    const float* pf = ibase + (size_t)(row0 + 3) * IMG_W;

    #pragma unroll
    for (int i = 0; i < RPT; i++) {
        // Raw prefetch row row0+i+3 (consumed 2 iterations later).
        Raw8 nraw;
        if (i < RPT - 2)
            nraw = load_raw8(pf, row0 + i + 3 < IMG_H, tid, lane);
        pf += IMG_W;

        float o[8];
        #pragma unroll
        for (int j = 0; j < 8; j++) {
            float gx = (top[j + 2] - top[j])
                     + 2.0f * (mid[j + 2] - mid[j])
                     + (bot[j + 2] - bot[j]);
            float gy = (bot[j]     - top[j])
                     + 2.0f * (bot[j + 1] - top[j + 1])
                     + (bot[j + 2] - top[j + 2]);
            o[j] = fabsf(gx) + fabsf(gy) + 1e-5f;
        }
        __stcs(reinterpret_cast<float4*>(obase),     make_float4(o[0], o[1], o[2], o[3]));
        __stcs(reinterpret_cast<float4*>(obase + 4), make_float4(o[4], o[5], o[6], o[7]));
        obase += IMG_W;

        if (i < RPT - 1) {
            #pragma unroll
            for (int k = 0; k < 10; k++) { top[k] = mid[k]; mid[k] = bot[k]; }
            expand8(praw, lane, bot);
            praw = nraw;
        }
    }
}

extern "C" void kernel_launch(void* const* d_in, const int* in_sizes, int n_in,
                              void* d_out, int out_size) {
    const float* x = (const float*)d_in[0];
    float* out = (float*)d_out;

    int blocks = out_size / (IMG_W * RPT);   // 32 * 64 = 2048
    sobel_grad_kernel<<<blocks, TPB>>>(x, out);
}

// round 12
// speedup vs baseline: 1.2580x; 1.2580x over previous
#include <cuda_runtime.h>

// Sobel |gx|+|gy|+eps over (32,1,1024,1024) f32, SAME zero padding.
// Warp-private cp.async ring: each warp owns a 128-float column segment and
// stages rows (with left/right halo) into its own 8-slot smem ring via
// cp.async. Producer == consumer warp, so sync is wait_group + __syncwarp
// only — no block barriers. 3-row rolling register window, ~4 rows in
// flight per warp at ZERO register cost.

#define IMG_W 1024
#define IMG_H 1024
#define TPB   256
#define RPT   16             // output rows per block
#define RB    (IMG_H / RPT)  // 64 row-blocks per image
#define S     8              // ring slots per warp
#define SLOT  136            // floats/slot: [3]=left halo, [4..131]=seg, [132]=right halo
#define WARPS (TPB / 32)

__device__ __forceinline__ void cp_async16(float* dst, const float* src) {
    unsigned sa = (unsigned)__cvta_generic_to_shared(dst);
    asm volatile("cp.async.cg.shared.global [%0], [%1], 16;"
                 :: "r"(sa), "l"(src) : "memory");
}
__device__ __forceinline__ void cp_async4(float* dst, const float* src) {
    unsigned sa = (unsigned)__cvta_generic_to_shared(dst);
    asm volatile("cp.async.ca.shared.global [%0], [%1], 4;"
                 :: "r"(sa), "l"(src) : "memory");
}
__device__ __forceinline__ void cp_commit() {
    asm volatile("cp.async.commit_group;" ::: "memory");
}
template <int N>
__device__ __forceinline__ void cp_wait() {
    asm volatile("cp.async.wait_group %0;" :: "n"(N) : "memory");
}

__global__ void __launch_bounds__(TPB)
sobel_grad_kernel(const float* __restrict__ x, float* __restrict__ out) {
    __shared__ float sm[WARPS][S][SLOT];

    int tid  = threadIdx.x;
    int w    = tid >> 5;           // warp = column segment (0..7)
    int lane = tid & 31;
    int bid  = blockIdx.x;
    int rb   = bid & (RB - 1);     // row block (0..63)
    int n    = bid >> 6;           // image     (0..31)
    int row0 = rb * RPT;

    const float* img = x + (size_t)n * IMG_H * IMG_W;
    const float* seg = img + w * 128;          // segment base within a row

    // stage rel row j (global row row0-1+j) into slot j&7; one commit/call
    auto stage = [&](int j) {
        int r = row0 - 1 + j;
        float* dst = &sm[w][j & (S - 1)][0];
        if ((unsigned)r < (unsigned)IMG_H) {
            const float* src = seg + (size_t)r * IMG_W + 4 * lane;
            cp_async16(dst + 4 + 4 * lane, src);
            if (lane == 0) {
                if (w > 0) cp_async4(dst + 3, src - 1);
                else       dst[3] = 0.0f;
            } else if (lane == 31) {
                if (w < WARPS - 1) cp_async4(dst + 132, src + 4);
                else               dst[132] = 0.0f;
            }
        } else {
            *reinterpret_cast<float4*>(dst + 4 + 4 * lane) =
                make_float4(0.f, 0.f, 0.f, 0.f);
            if (lane == 0)  dst[3]   = 0.0f;
            if (lane == 31) dst[132] = 0.0f;
        }
        cp_commit();
    };

    auto read6 = [&](int j, float v[6]) {
        const float* p = &sm[w][j & (S - 1)][4 + 4 * lane];
        float4 c = *reinterpret_cast<const float4*>(p);
        v[0] = p[-1]; v[1] = c.x; v[2] = c.y; v[3] = c.z; v[4] = c.w; v[5] = p[4];
    };

    // Prologue: stage rel rows 0..6 (rows row0-1 .. row0+5).
    #pragma unroll
    for (int j = 0; j < 7; j++) stage(j);

    cp_wait<4>();          // rel rows 0,1,2 arrived
    __syncwarp();

    float top[6], mid[6], bot[6];
    read6(0, top);
    read6(1, mid);
    read6(2, bot);

    float* op = out + (size_t)n * IMG_H * IMG_W + (size_t)row0 * IMG_W
                    + w * 128 + 4 * lane;

    #pragma unroll
    for (int i = 0; i < RPT; i++) {
        // Keep the ring fed: stage rel row i+7 (row row0+i+6); empty commit
        // once past the last needed row to keep group accounting uniform.
        if (i + 7 <= RPT + 1) stage(i + 7);
        else                  cp_commit();

        float o0, o1, o2, o3;
        {
            float gx, gy;
            gx = (top[2] - top[0]) + 2.0f * (mid[2] - mid[0]) + (bot[2] - bot[0]);
            gy = (bot[0] - top[0]) + 2.0f * (bot[1] - top[1]) + (bot[2] - top[2]);
            o0 = fabsf(gx) + fabsf(gy) + 1e-5f;
            gx = (top[3] - top[1]) + 2.0f * (mid[3] - mid[1]) + (bot[3] - bot[1]);
            gy = (bot[1] - top[1]) + 2.0f * (bot[2] - top[2]) + (bot[3] - top[3]);
            o1 = fabsf(gx) + fabsf(gy) + 1e-5f;
            gx = (top[4] - top[2]) + 2.0f * (mid[4] - mid[2]) + (bot[4] - bot[2]);
            gy = (bot[2] - top[2]) + 2.0f * (bot[3] - top[3]) + (bot[4] - top[4]);
            o2 = fabsf(gx) + fabsf(gy) + 1e-5f;
            gx = (top[5] - top[3]) + 2.0f * (mid[5] - mid[3]) + (bot[5] - bot[3]);
            gy = (bot[3] - top[3]) + 2.0f * (bot[4] - top[4]) + (bot[5] - top[5]);
            o3 = fabsf(gx) + fabsf(gy) + 1e-5f;
        }
        __stcs(reinterpret_cast<float4*>(op), make_float4(o0, o1, o2, o3));
        op += IMG_W;

        if (i < RPT - 1) {
            // rel row i+3 (the next bot) is complete once <=4 groups pend.
            cp_wait<4>();
            __syncwarp();
            #pragma unroll
            for (int k = 0; k < 6; k++) { top[k] = mid[k]; mid[k] = bot[k]; }
            read6(i + 3, bot);
        }
    }
}

extern "C" void kernel_launch(void* const* d_in, const int* in_sizes, int n_in,
                              void* d_out, int out_size) {
    const float* x = (const float*)d_in[0];
    float* out = (float*)d_out;

    int blocks = out_size / (IMG_W * RPT);   // 32 images * 64 row-blocks = 2048
    sobel_grad_kernel<<<blocks, TPB>>>(x, out);
}